// round 12
// baseline (speedup 1.0000x reference)
#include <cuda_runtime.h>
#include <cuda_fp16.h>

#define DK 32
#define ODIM 32
#define MAX_NODES 100002
#define MAX_N 100000
#define NPW 2            // nodes per warp
#define WPB 4            // warps per block (block = 128 threads)

// Scratch (device globals — no allocation in kernel_launch)
__device__ int g_row_ptr[MAX_NODES];
// Packed per-node 128B line of 16B chunks; chunk qd = [K' quad qd | V' quad qd]
// halves, where K' = K/DK (scale folded) and V' = V @ Wo (projection folded).
__device__ __align__(16) __half g_KV[MAX_N * 2 * DK];

// ---------------------------------------------------------------------------
// Prep kernel (fused, 3 block ranges):
//   [0, kpackBlocks)             : pack K/DK quads to fp16 (8B writes)
//   [kpackBlocks, +vprojBlocks)  : V' = V @ Wo, packed fp16 into V-half
//   remainder                    : CSR row pointers (4 edges/thread, int4)
// ---------------------------------------------------------------------------
__global__ __launch_bounds__(256) void prep_kernel(
    const float* __restrict__ Kf,
    const float* __restrict__ Vf,
    const float* __restrict__ Wo,
    const int*   __restrict__ dst,
    int N, int E, int kpackBlocks, int vprojBlocks)
{
    __shared__ float4 sWoT4[ODIM][9];                 // sWoT4[c][dq] = Wo[4dq..][c]
    __shared__ __align__(16) float sV[64 * DK];       // 64-node V tile

    const int b = (int)blockIdx.x;
    if (b < kpackBlocks) {
        // ---- K pack: one K quad (4 halves = 8B) per thread, scaled by 1/DK ----
        const int c = b * 256 + threadIdx.x;
        if (c >= N * 8) return;
        const int node = c >> 3;
        const int qd   = c & 7;
        const float4 kq = *reinterpret_cast<const float4*>(Kf + (size_t)node * DK + qd * 4);
        __half2 h0 = __floats2half2_rn(kq.x * (1.f/DK), kq.y * (1.f/DK));
        __half2 h1 = __floats2half2_rn(kq.z * (1.f/DK), kq.w * (1.f/DK));
        uint2 o;
        o.x = *reinterpret_cast<unsigned*>(&h0);
        o.y = *reinterpret_cast<unsigned*>(&h1);
        reinterpret_cast<uint2*>(g_KV)[(size_t)node * 16 + qd * 2] = o;
    } else if (b < kpackBlocks + vprojBlocks) {
        // ---- V' = V @ Wo for a 64-node tile; write fp16 into V-half ----
        for (int i = threadIdx.x; i < DK * ODIM; i += 256) {
            const int d = i >> 5, c = i & 31;
            reinterpret_cast<float*>(&sWoT4[c][0])[d] = Wo[i];
        }
        const int tile = (b - kpackBlocks) * 64;
        for (int i = threadIdx.x; i < 64 * DK / 4; i += 256) {
            const int gidx = tile * (DK / 4) + i;
            float4 v = make_float4(0.f, 0.f, 0.f, 0.f);
            if (gidx < N * (DK / 4))
                v = reinterpret_cast<const float4*>(Vf)[gidx];
            reinterpret_cast<float4*>(sV)[i] = v;
        }
        __syncthreads();

        const int lane = threadIdx.x & 31;     // output column c
        const int w    = threadIdx.x >> 5;     // warp -> local nodes 8w..8w+7

        float o[8];
        #pragma unroll
        for (int n = 0; n < 8; ++n) o[n] = 0.f;
        #pragma unroll
        for (int dq = 0; dq < 8; ++dq) {
            const float4 wt = sWoT4[lane][dq];
            #pragma unroll
            for (int n = 0; n < 8; ++n) {
                const float4 a = *reinterpret_cast<const float4*>(&sV[(w * 8 + n) * DK + dq * 4]);
                o[n] += a.x * wt.x + a.y * wt.y + a.z * wt.z + a.w * wt.w;
            }
        }
        #pragma unroll
        for (int n = 0; n < 8; ++n) {
            const int node = tile + w * 8 + n;
            if (node < N) {
                g_KV[(size_t)node * 64 + (lane >> 2) * 8 + 4 + (lane & 3)] =
                    __float2half_rn(o[n]);
            }
        }
    } else {
        // ---- Row pointers: 4 edges per thread ----
        const int t  = (b - kpackBlocks - vprojBlocks) * 256 + threadIdx.x;
        const int e0 = t * 4;
        if (e0 >= E) return;
        int ds[4];
        if (e0 + 3 < E) {
            const int4 d4 = *reinterpret_cast<const int4*>(dst + e0);
            ds[0] = d4.x; ds[1] = d4.y; ds[2] = d4.z; ds[3] = d4.w;
        } else {
            #pragma unroll
            for (int j = 0; j < 4; ++j) ds[j] = (e0 + j < E) ? dst[e0 + j] : 0;
        }
        int p = (e0 > 0) ? dst[e0 - 1] : -1;
        #pragma unroll
        for (int j = 0; j < 4; ++j) {
            const int e = e0 + j;
            if (e < E) {
                const int d = ds[j];
                for (int n = p + 1; n <= d; ++n) g_row_ptr[n] = e;
                p = d;
                if (e == E - 1)
                    for (int n = d + 1; n <= N; ++n) g_row_ptr[n] = E;
            }
        }
    }
}

// ---------------------------------------------------------------------------
// Fused gat kernel: one warp per NPW nodes; 8-lane groups fetch ONE packed
// [K'|V'] line per edge. Single 4-edge sub-batch per iteration, masked-always
// (no duplicated tail). Epilogue = group reduce + rcp + one 128B store.
// ---------------------------------------------------------------------------
__global__ __launch_bounds__(128, 12) void gat_kernel(
    const float* __restrict__ X,
    const float* __restrict__ bo,
    const int*   __restrict__ src,
    float* __restrict__ out,
    int N)
{
    const unsigned FULL = 0xffffffffu;
    const int lane = threadIdx.x & 31;
    const int warp = (blockIdx.x * blockDim.x + threadIdx.x) >> 5;
    const int node0 = warp * NPW;
    if (node0 >= N) return;

    const int g  = lane >> 3;   // edge slot within the 4-edge batch
    const int qd = lane & 7;    // quad (4 dims) this lane covers

    // Bias quad for the store lanes.
    float4 bq = make_float4(0.f, 0.f, 0.f, 0.f);
    if (lane < 8) bq = reinterpret_cast<const float4*>(bo)[lane];

    #pragma unroll 1
    for (int ni = 0; ni < NPW; ++ni) {
        const int node = node0 + ni;
        if (node >= N) break;
        const int beg = g_row_ptr[node];
        const int end = g_row_ptr[node + 1];

        // Query quad (raw — 1/DK folded into K').
        const float4 q4 = *reinterpret_cast<const float4*>(X + (size_t)node * DK + qd * 4);

        float4 acc = make_float4(0.f, 0.f, 0.f, 0.f);
        float lsum = 0.f;
        const int last = end - 1;

        #pragma unroll 1
        for (int base = beg; base < end; base += 4) {
            const int e = base + g;
            const unsigned o = (unsigned)__ldg(&src[min(e, last)]) * 8u + qd;
            const uint4 h = reinterpret_cast<const uint4*>(g_KV)[o];

            const float2 k0 = __half22float2(*reinterpret_cast<const __half2*>(&h.x));
            const float2 k1 = __half22float2(*reinterpret_cast<const __half2*>(&h.y));

            float d = q4.x*k0.x + q4.y*k0.y + q4.z*k1.x + q4.w*k1.y;
            d += __shfl_xor_sync(FULL, d, 1);
            d += __shfl_xor_sync(FULL, d, 2);
            d += __shfl_xor_sync(FULL, d, 4);

            const float p = (e < end) ? __expf(d) : 0.f;
            lsum += p;

            const float2 v0 = __half22float2(*reinterpret_cast<const __half2*>(&h.z));
            const float2 v1 = __half22float2(*reinterpret_cast<const __half2*>(&h.w));
            acc.x += p * v0.x;
            acc.y += p * v0.y;
            acc.z += p * v1.x;
            acc.w += p * v1.y;
        }

        // Reduce acc + lsum across the 4 edge-groups (bits 3,4 only).
        #pragma unroll
        for (int o = 8; o <= 16; o <<= 1) {
            acc.x += __shfl_xor_sync(FULL, acc.x, o);
            acc.y += __shfl_xor_sync(FULL, acc.y, o);
            acc.z += __shfl_xor_sync(FULL, acc.z, o);
            acc.w += __shfl_xor_sync(FULL, acc.w, o);
            lsum  += __shfl_xor_sync(FULL, lsum,  o);
        }
        const float inv = (lsum > 0.f) ? (1.f / lsum) : 0.f;

        // Projection already folded into V': lanes 0..7 hold output quads 0..7.
        if (lane < 8) {
            float4 r;
            r.x = acc.x * inv + bq.x;
            r.y = acc.y * inv + bq.y;
            r.z = acc.z * inv + bq.z;
            r.w = acc.w * inv + bq.w;
            *reinterpret_cast<float4*>(&out[(size_t)node * ODIM + lane * 4]) = r;
        }
    }
}

extern "C" void kernel_launch(void* const* d_in, const int* in_sizes, int n_in,
                              void* d_out, int out_size) {
    const float* X   = (const float*)d_in[0];
    const float* K   = (const float*)d_in[1];
    const float* V   = (const float*)d_in[2];
    const float* Wo  = (const float*)d_in[3];
    const float* bo  = (const float*)d_in[4];
    const int*   src = (const int*)d_in[5];
    const int*   dst = (const int*)d_in[6];

    const int N = in_sizes[0] / DK;   // 100000
    const int E = in_sizes[5];        // 1600000

    const int kpackBlocks = (N * 8 + 255) / 256;         // 3125
    const int vprojBlocks = (N + 63) / 64;               // 1563
    const int rpBlocks    = ((E + 3) / 4 + 255) / 256;   // 1563
    prep_kernel<<<kpackBlocks + vprojBlocks + rpBlocks, 256>>>(
        K, V, Wo, dst, N, E, kpackBlocks, vprojBlocks);

    const int warps  = (N + NPW - 1) / NPW;              // 50000
    const int blocks = (warps + WPB - 1) / WPB;          // 12500
    gat_kernel<<<blocks, 32 * WPB>>>(X, bo, src, (float*)d_out, N);
}

// round 13
// speedup vs baseline: 1.0896x; 1.0896x over previous
#include <cuda_runtime.h>
#include <cuda_fp16.h>

#define DK 32
#define ODIM 32
#define MAX_NODES 100002
#define MAX_N 100000
#define WPB 4            // warps per block (block = 128 threads)

// Scratch (device globals — no allocation in kernel_launch)
__device__ int g_row_ptr[MAX_NODES];
// Packed per-node 128B line of 16B chunks; chunk qd = [K' quad qd | V' quad qd]
// halves, where K' = K/DK (scale folded) and V' = V @ Wo (projection folded).
__device__ __align__(16) __half g_KV[MAX_N * 2 * DK];

// ---------------------------------------------------------------------------
// Prep kernel (fused, 3 block ranges):
//   [0, kpackBlocks)             : pack K/DK quads to fp16 (8B writes)
//   [kpackBlocks, +vprojBlocks)  : V' = V @ Wo, packed fp16 into V-half
//   remainder                    : CSR row pointers (4 edges/thread, int4)
// ---------------------------------------------------------------------------
__global__ __launch_bounds__(256) void prep_kernel(
    const float* __restrict__ Kf,
    const float* __restrict__ Vf,
    const float* __restrict__ Wo,
    const int*   __restrict__ dst,
    int N, int E, int kpackBlocks, int vprojBlocks)
{
    __shared__ float4 sWoT4[ODIM][9];                 // sWoT4[c][dq] = Wo[4dq..][c]
    __shared__ __align__(16) float sV[64 * DK];       // 64-node V tile

    const int b = (int)blockIdx.x;
    if (b < kpackBlocks) {
        // ---- K pack: one K quad (4 halves = 8B) per thread, scaled by 1/DK ----
        const int c = b * 256 + threadIdx.x;
        if (c >= N * 8) return;
        const int node = c >> 3;
        const int qd   = c & 7;
        const float4 kq = *reinterpret_cast<const float4*>(Kf + (size_t)node * DK + qd * 4);
        __half2 h0 = __floats2half2_rn(kq.x * (1.f/DK), kq.y * (1.f/DK));
        __half2 h1 = __floats2half2_rn(kq.z * (1.f/DK), kq.w * (1.f/DK));
        uint2 o;
        o.x = *reinterpret_cast<unsigned*>(&h0);
        o.y = *reinterpret_cast<unsigned*>(&h1);
        reinterpret_cast<uint2*>(g_KV)[(size_t)node * 16 + qd * 2] = o;
    } else if (b < kpackBlocks + vprojBlocks) {
        // ---- V' = V @ Wo for a 64-node tile; write fp16 into V-half ----
        for (int i = threadIdx.x; i < DK * ODIM; i += 256) {
            const int d = i >> 5, c = i & 31;
            reinterpret_cast<float*>(&sWoT4[c][0])[d] = Wo[i];
        }
        const int tile = (b - kpackBlocks) * 64;
        for (int i = threadIdx.x; i < 64 * DK / 4; i += 256) {
            const int gidx = tile * (DK / 4) + i;
            float4 v = make_float4(0.f, 0.f, 0.f, 0.f);
            if (gidx < N * (DK / 4))
                v = reinterpret_cast<const float4*>(Vf)[gidx];
            reinterpret_cast<float4*>(sV)[i] = v;
        }
        __syncthreads();

        const int lane = threadIdx.x & 31;     // output column c
        const int w    = threadIdx.x >> 5;     // warp -> local nodes 8w..8w+7

        float o[8];
        #pragma unroll
        for (int n = 0; n < 8; ++n) o[n] = 0.f;
        #pragma unroll
        for (int dq = 0; dq < 8; ++dq) {
            const float4 wt = sWoT4[lane][dq];
            #pragma unroll
            for (int n = 0; n < 8; ++n) {
                const float4 a = *reinterpret_cast<const float4*>(&sV[(w * 8 + n) * DK + dq * 4]);
                o[n] += a.x * wt.x + a.y * wt.y + a.z * wt.z + a.w * wt.w;
            }
        }
        #pragma unroll
        for (int n = 0; n < 8; ++n) {
            const int node = tile + w * 8 + n;
            if (node < N) {
                g_KV[(size_t)node * 64 + (lane >> 2) * 8 + 4 + (lane & 3)] =
                    __float2half_rn(o[n]);
            }
        }
    } else {
        // ---- Row pointers: 4 edges per thread ----
        const int t  = (b - kpackBlocks - vprojBlocks) * 256 + threadIdx.x;
        const int e0 = t * 4;
        if (e0 >= E) return;
        int ds[4];
        if (e0 + 3 < E) {
            const int4 d4 = *reinterpret_cast<const int4*>(dst + e0);
            ds[0] = d4.x; ds[1] = d4.y; ds[2] = d4.z; ds[3] = d4.w;
        } else {
            #pragma unroll
            for (int j = 0; j < 4; ++j) ds[j] = (e0 + j < E) ? dst[e0 + j] : 0;
        }
        int p = (e0 > 0) ? dst[e0 - 1] : -1;
        #pragma unroll
        for (int j = 0; j < 4; ++j) {
            const int e = e0 + j;
            if (e < E) {
                const int d = ds[j];
                for (int n = p + 1; n <= d; ++n) g_row_ptr[n] = e;
                p = d;
                if (e == E - 1)
                    for (int n = d + 1; n <= N; ++n) g_row_ptr[n] = E;
            }
        }
    }
}

// ---------------------------------------------------------------------------
// Fused gat kernel: ONE warp per node; 8-lane groups fetch ONE packed [K'|V']
// line per edge; two independent 4-edge sub-batches per iteration (MLP=2).
// Epilogue = group reduce + rcp + one 128B store. No smem, no block sync.
// ---------------------------------------------------------------------------
__global__ __launch_bounds__(128, 12) void gat_kernel(
    const float* __restrict__ X,
    const float* __restrict__ bo,
    const int*   __restrict__ src,
    float* __restrict__ out,
    int N)
{
    const unsigned FULL = 0xffffffffu;
    const int lane = threadIdx.x & 31;
    const int node = (blockIdx.x * blockDim.x + threadIdx.x) >> 5;
    if (node >= N) return;

    const int g  = lane >> 3;   // edge slot within a 4-edge sub-batch
    const int qd = lane & 7;    // quad (4 dims) this lane covers

    // Bias quad for the store lanes.
    float4 bq = make_float4(0.f, 0.f, 0.f, 0.f);
    if (lane < 8) bq = reinterpret_cast<const float4*>(bo)[lane];

    const int beg = g_row_ptr[node];
    const int end = g_row_ptr[node + 1];

    // Query quad (raw — 1/DK folded into K').
    const float4 q4 = *reinterpret_cast<const float4*>(X + (size_t)node * DK + qd * 4);

    float4 acc = make_float4(0.f, 0.f, 0.f, 0.f);
    float lsum = 0.f;

    int base = beg;
    // Full (unmasked) iterations: 8 edges = 2 independent sub-batches of 4.
    #pragma unroll 1
    for (; base + 8 <= end; base += 8) {
        const unsigned oA = (unsigned)__ldg(&src[base + g])     * 8u + qd;
        const unsigned oB = (unsigned)__ldg(&src[base + 4 + g]) * 8u + qd;
        const uint4 ha = reinterpret_cast<const uint4*>(g_KV)[oA];
        const uint4 hb = reinterpret_cast<const uint4*>(g_KV)[oB];

        const float2 ka0 = __half22float2(*reinterpret_cast<const __half2*>(&ha.x));
        const float2 ka1 = __half22float2(*reinterpret_cast<const __half2*>(&ha.y));
        const float2 kb0 = __half22float2(*reinterpret_cast<const __half2*>(&hb.x));
        const float2 kb1 = __half22float2(*reinterpret_cast<const __half2*>(&hb.y));

        float dA = q4.x*ka0.x + q4.y*ka0.y + q4.z*ka1.x + q4.w*ka1.y;
        float dB = q4.x*kb0.x + q4.y*kb0.y + q4.z*kb1.x + q4.w*kb1.y;
        #pragma unroll
        for (int o = 1; o <= 4; o <<= 1) {
            dA += __shfl_xor_sync(FULL, dA, o);
            dB += __shfl_xor_sync(FULL, dB, o);
        }
        const float pA = __expf(dA);
        const float pB = __expf(dB);
        lsum += pA + pB;

        const float2 va0 = __half22float2(*reinterpret_cast<const __half2*>(&ha.z));
        const float2 va1 = __half22float2(*reinterpret_cast<const __half2*>(&ha.w));
        const float2 vb0 = __half22float2(*reinterpret_cast<const __half2*>(&hb.z));
        const float2 vb1 = __half22float2(*reinterpret_cast<const __half2*>(&hb.w));
        acc.x += pA * va0.x + pB * vb0.x;
        acc.y += pA * va0.y + pB * vb0.y;
        acc.z += pA * va1.x + pB * vb1.x;
        acc.w += pA * va1.y + pB * vb1.y;
    }

    // One masked tail iteration.
    if (base < end) {
        const int eA = base + g;
        const int eB = base + 4 + g;
        const bool mA = (eA < end);
        const bool mB = (eB < end);
        const unsigned oA = (unsigned)__ldg(&src[mA ? eA : beg]) * 8u + qd;
        const unsigned oB = (unsigned)__ldg(&src[mB ? eB : beg]) * 8u + qd;
        const uint4 ha = reinterpret_cast<const uint4*>(g_KV)[oA];
        const uint4 hb = reinterpret_cast<const uint4*>(g_KV)[oB];

        const float2 ka0 = __half22float2(*reinterpret_cast<const __half2*>(&ha.x));
        const float2 ka1 = __half22float2(*reinterpret_cast<const __half2*>(&ha.y));
        const float2 kb0 = __half22float2(*reinterpret_cast<const __half2*>(&hb.x));
        const float2 kb1 = __half22float2(*reinterpret_cast<const __half2*>(&hb.y));

        float dA = q4.x*ka0.x + q4.y*ka0.y + q4.z*ka1.x + q4.w*ka1.y;
        float dB = q4.x*kb0.x + q4.y*kb0.y + q4.z*kb1.x + q4.w*kb1.y;
        #pragma unroll
        for (int o = 1; o <= 4; o <<= 1) {
            dA += __shfl_xor_sync(FULL, dA, o);
            dB += __shfl_xor_sync(FULL, dB, o);
        }
        const float pA = mA ? __expf(dA) : 0.f;
        const float pB = mB ? __expf(dB) : 0.f;
        lsum += pA + pB;

        const float2 va0 = __half22float2(*reinterpret_cast<const __half2*>(&ha.z));
        const float2 va1 = __half22float2(*reinterpret_cast<const __half2*>(&ha.w));
        const float2 vb0 = __half22float2(*reinterpret_cast<const __half2*>(&hb.z));
        const float2 vb1 = __half22float2(*reinterpret_cast<const __half2*>(&hb.w));
        acc.x += pA * va0.x + pB * vb0.x;
        acc.y += pA * va0.y + pB * vb0.y;
        acc.z += pA * va1.x + pB * vb1.x;
        acc.w += pA * va1.y + pB * vb1.y;
    }

    // Reduce acc + lsum across the 4 edge-groups (bits 3,4 only).
    #pragma unroll
    for (int o = 8; o <= 16; o <<= 1) {
        acc.x += __shfl_xor_sync(FULL, acc.x, o);
        acc.y += __shfl_xor_sync(FULL, acc.y, o);
        acc.z += __shfl_xor_sync(FULL, acc.z, o);
        acc.w += __shfl_xor_sync(FULL, acc.w, o);
        lsum  += __shfl_xor_sync(FULL, lsum,  o);
    }
    const float inv = (lsum > 0.f) ? (1.f / lsum) : 0.f;

    // Projection already folded into V': lanes 0..7 hold output quads 0..7.
    if (lane < 8) {
        float4 r;
        r.x = acc.x * inv + bq.x;
        r.y = acc.y * inv + bq.y;
        r.z = acc.z * inv + bq.z;
        r.w = acc.w * inv + bq.w;
        *reinterpret_cast<float4*>(&out[(size_t)node * ODIM + lane * 4]) = r;
    }
}

extern "C" void kernel_launch(void* const* d_in, const int* in_sizes, int n_in,
                              void* d_out, int out_size) {
    const float* X   = (const float*)d_in[0];
    const float* K   = (const float*)d_in[1];
    const float* V   = (const float*)d_in[2];
    const float* Wo  = (const float*)d_in[3];
    const float* bo  = (const float*)d_in[4];
    const int*   src = (const int*)d_in[5];
    const int*   dst = (const int*)d_in[6];

    const int N = in_sizes[0] / DK;   // 100000
    const int E = in_sizes[5];        // 1600000

    const int kpackBlocks = (N * 8 + 255) / 256;         // 3125
    const int vprojBlocks = (N + 63) / 64;               // 1563
    const int rpBlocks    = ((E + 3) / 4 + 255) / 256;   // 1563
    prep_kernel<<<kpackBlocks + vprojBlocks + rpBlocks, 256>>>(
        K, V, Wo, dst, N, E, kpackBlocks, vprojBlocks);

    const int blocks = (N + WPB - 1) / WPB;              // one warp per node; 25000
    gat_kernel<<<blocks, 32 * WPB>>>(X, bo, src, (float*)d_out, N);
}

// round 14
// speedup vs baseline: 1.1242x; 1.0318x over previous
#include <cuda_runtime.h>
#include <cuda_fp16.h>

#define DK 32
#define ODIM 32
#define MAX_NODES 100002
#define MAX_N 100000
#define WPB 4            // warps per block (block = 128 threads)

// Scratch (device globals — no allocation in kernel_launch)
__device__ int g_row_ptr[MAX_NODES];
// Packed per-node 128B line of 16B chunks; chunk qd = [K' quad qd | V' quad qd]
// halves, where K' = K/DK (scale folded) and V' = V @ Wo (projection folded).
__device__ __align__(16) __half g_KV[MAX_N * 2 * DK];

// ---------------------------------------------------------------------------
// Prep kernel (fused, 2 block ranges):
//   [0, vkBlocks)  : per 64-node tile — pack K'/DK + compute V' = V @ Wo,
//                    stage both in smem, write full 128B lines coalesced.
//   remainder      : CSR row pointers (4 edges/thread, int4)
// ---------------------------------------------------------------------------
__global__ __launch_bounds__(256) void prep_kernel(
    const float* __restrict__ Kf,
    const float* __restrict__ Vf,
    const float* __restrict__ Wo,
    const int*   __restrict__ dst,
    int N, int E, int vkBlocks)
{
    __shared__ float4 sWoT4[ODIM][9];                  // sWoT4[c][dq] = Wo[4dq..][c]
    __shared__ __align__(16) float sV[64 * DK];        // 64-node V tile
    __shared__ __align__(16) __half sPack[64 * 64];    // staged [K'|V'] lines

    const int b = (int)blockIdx.x;
    if (b < vkBlocks) {
        const int tile = b * 64;
        const int tid  = threadIdx.x;

        // Load Wo (transposed, padded).
        for (int i = tid; i < DK * ODIM; i += 256) {
            const int d = i >> 5, c = i & 31;
            reinterpret_cast<float*>(&sWoT4[c][0])[d] = Wo[i];
        }
        // Load V tile (64 nodes x 32 f32 = 512 float4s).
        for (int i = tid; i < 64 * DK / 4; i += 256) {
            const int gidx = tile * (DK / 4) + i;
            float4 v = make_float4(0.f, 0.f, 0.f, 0.f);
            if (gidx < N * (DK / 4))
                v = reinterpret_cast<const float4*>(Vf)[gidx];
            reinterpret_cast<float4*>(sV)[i] = v;
        }
        // Pack K'/DK quads into staging (coalesced 16B reads, 8B smem writes).
        for (int i = tid; i < 64 * 8; i += 256) {
            const int nl = i >> 3;        // local node
            const int qd = i & 7;
            const int gn = tile + nl;
            if (gn < N) {
                const float4 kq = reinterpret_cast<const float4*>(Kf)[(size_t)gn * 8 + qd];
                __half2 h0 = __floats2half2_rn(kq.x * (1.f/DK), kq.y * (1.f/DK));
                __half2 h1 = __floats2half2_rn(kq.z * (1.f/DK), kq.w * (1.f/DK));
                uint2 o;
                o.x = *reinterpret_cast<unsigned*>(&h0);
                o.y = *reinterpret_cast<unsigned*>(&h1);
                *reinterpret_cast<uint2*>(&sPack[nl * 64 + qd * 8]) = o;
            }
        }
        __syncthreads();

        // V' = V @ Wo : warp w -> local nodes 8w..8w+7, lane = output col c.
        {
            const int lane = threadIdx.x & 31;
            const int w    = threadIdx.x >> 5;
            float o[8];
            #pragma unroll
            for (int n = 0; n < 8; ++n) o[n] = 0.f;
            #pragma unroll
            for (int dq = 0; dq < 8; ++dq) {
                const float4 wt = sWoT4[lane][dq];
                #pragma unroll
                for (int n = 0; n < 8; ++n) {
                    const float4 a = *reinterpret_cast<const float4*>(&sV[(w * 8 + n) * DK + dq * 4]);
                    o[n] += a.x * wt.x + a.y * wt.y + a.z * wt.z + a.w * wt.w;
                }
            }
            // Stage V' halves: half idx nl*64 + (c>>2)*8 + 4 + (c&3).
            #pragma unroll
            for (int n = 0; n < 8; ++n)
                sPack[(w * 8 + n) * 64 + (lane >> 2) * 8 + 4 + (lane & 3)] =
                    __float2half_rn(o[n]);
        }
        __syncthreads();

        // Write full 128B lines, coalesced (512 uint4s).
        for (int i = tid; i < 64 * 8; i += 256) {
            const int nl = i >> 3;
            const int gn = tile + nl;
            if (gn < N)
                reinterpret_cast<uint4*>(g_KV)[(size_t)gn * 8 + (i & 7)] =
                    reinterpret_cast<const uint4*>(sPack)[i];
        }
    } else {
        // ---- Row pointers: 4 edges per thread ----
        const int t  = (b - vkBlocks) * 256 + threadIdx.x;
        const int e0 = t * 4;
        if (e0 >= E) return;
        int ds[4];
        if (e0 + 3 < E) {
            const int4 d4 = *reinterpret_cast<const int4*>(dst + e0);
            ds[0] = d4.x; ds[1] = d4.y; ds[2] = d4.z; ds[3] = d4.w;
        } else {
            #pragma unroll
            for (int j = 0; j < 4; ++j) ds[j] = (e0 + j < E) ? dst[e0 + j] : 0;
        }
        int p = (e0 > 0) ? dst[e0 - 1] : -1;
        #pragma unroll
        for (int j = 0; j < 4; ++j) {
            const int e = e0 + j;
            if (e < E) {
                const int d = ds[j];
                for (int n = p + 1; n <= d; ++n) g_row_ptr[n] = e;
                p = d;
                if (e == E - 1)
                    for (int n = d + 1; n <= N; ++n) g_row_ptr[n] = E;
            }
        }
    }
}

// ---------------------------------------------------------------------------
// Fused gat kernel (unchanged from best-measured R13): ONE warp per node;
// 8-lane groups fetch ONE packed [K'|V'] line per edge; two independent
// 4-edge sub-batches per iteration (MLP=2). Epilogue = reduce + rcp + store.
// ---------------------------------------------------------------------------
__global__ __launch_bounds__(128, 12) void gat_kernel(
    const float* __restrict__ X,
    const float* __restrict__ bo,
    const int*   __restrict__ src,
    float* __restrict__ out,
    int N)
{
    const unsigned FULL = 0xffffffffu;
    const int lane = threadIdx.x & 31;
    const int node = (blockIdx.x * blockDim.x + threadIdx.x) >> 5;
    if (node >= N) return;

    const int g  = lane >> 3;   // edge slot within a 4-edge sub-batch
    const int qd = lane & 7;    // quad (4 dims) this lane covers

    float4 bq = make_float4(0.f, 0.f, 0.f, 0.f);
    if (lane < 8) bq = reinterpret_cast<const float4*>(bo)[lane];

    const int beg = g_row_ptr[node];
    const int end = g_row_ptr[node + 1];

    const float4 q4 = *reinterpret_cast<const float4*>(X + (size_t)node * DK + qd * 4);

    float4 acc = make_float4(0.f, 0.f, 0.f, 0.f);
    float lsum = 0.f;

    int base = beg;
    #pragma unroll 1
    for (; base + 8 <= end; base += 8) {
        const unsigned oA = (unsigned)__ldg(&src[base + g])     * 8u + qd;
        const unsigned oB = (unsigned)__ldg(&src[base + 4 + g]) * 8u + qd;
        const uint4 ha = reinterpret_cast<const uint4*>(g_KV)[oA];
        const uint4 hb = reinterpret_cast<const uint4*>(g_KV)[oB];

        const float2 ka0 = __half22float2(*reinterpret_cast<const __half2*>(&ha.x));
        const float2 ka1 = __half22float2(*reinterpret_cast<const __half2*>(&ha.y));
        const float2 kb0 = __half22float2(*reinterpret_cast<const __half2*>(&hb.x));
        const float2 kb1 = __half22float2(*reinterpret_cast<const __half2*>(&hb.y));

        float dA = q4.x*ka0.x + q4.y*ka0.y + q4.z*ka1.x + q4.w*ka1.y;
        float dB = q4.x*kb0.x + q4.y*kb0.y + q4.z*kb1.x + q4.w*kb1.y;
        #pragma unroll
        for (int o = 1; o <= 4; o <<= 1) {
            dA += __shfl_xor_sync(FULL, dA, o);
            dB += __shfl_xor_sync(FULL, dB, o);
        }
        const float pA = __expf(dA);
        const float pB = __expf(dB);
        lsum += pA + pB;

        const float2 va0 = __half22float2(*reinterpret_cast<const __half2*>(&ha.z));
        const float2 va1 = __half22float2(*reinterpret_cast<const __half2*>(&ha.w));
        const float2 vb0 = __half22float2(*reinterpret_cast<const __half2*>(&hb.z));
        const float2 vb1 = __half22float2(*reinterpret_cast<const __half2*>(&hb.w));
        acc.x += pA * va0.x + pB * vb0.x;
        acc.y += pA * va0.y + pB * vb0.y;
        acc.z += pA * va1.x + pB * vb1.x;
        acc.w += pA * va1.y + pB * vb1.y;
    }

    if (base < end) {
        const int eA = base + g;
        const int eB = base + 4 + g;
        const bool mA = (eA < end);
        const bool mB = (eB < end);
        const unsigned oA = (unsigned)__ldg(&src[mA ? eA : beg]) * 8u + qd;
        const unsigned oB = (unsigned)__ldg(&src[mB ? eB : beg]) * 8u + qd;
        const uint4 ha = reinterpret_cast<const uint4*>(g_KV)[oA];
        const uint4 hb = reinterpret_cast<const uint4*>(g_KV)[oB];

        const float2 ka0 = __half22float2(*reinterpret_cast<const __half2*>(&ha.x));
        const float2 ka1 = __half22float2(*reinterpret_cast<const __half2*>(&ha.y));
        const float2 kb0 = __half22float2(*reinterpret_cast<const __half2*>(&hb.x));
        const float2 kb1 = __half22float2(*reinterpret_cast<const __half2*>(&hb.y));

        float dA = q4.x*ka0.x + q4.y*ka0.y + q4.z*ka1.x + q4.w*ka1.y;
        float dB = q4.x*kb0.x + q4.y*kb0.y + q4.z*kb1.x + q4.w*kb1.y;
        #pragma unroll
        for (int o = 1; o <= 4; o <<= 1) {
            dA += __shfl_xor_sync(FULL, dA, o);
            dB += __shfl_xor_sync(FULL, dB, o);
        }
        const float pA = mA ? __expf(dA) : 0.f;
        const float pB = mB ? __expf(dB) : 0.f;
        lsum += pA + pB;

        const float2 va0 = __half22float2(*reinterpret_cast<const __half2*>(&ha.z));
        const float2 va1 = __half22float2(*reinterpret_cast<const __half2*>(&ha.w));
        const float2 vb0 = __half22float2(*reinterpret_cast<const __half2*>(&hb.z));
        const float2 vb1 = __half22float2(*reinterpret_cast<const __half2*>(&hb.w));
        acc.x += pA * va0.x + pB * vb0.x;
        acc.y += pA * va0.y + pB * vb0.y;
        acc.z += pA * va1.x + pB * vb1.x;
        acc.w += pA * va1.y + pB * vb1.y;
    }

    #pragma unroll
    for (int o = 8; o <= 16; o <<= 1) {
        acc.x += __shfl_xor_sync(FULL, acc.x, o);
        acc.y += __shfl_xor_sync(FULL, acc.y, o);
        acc.z += __shfl_xor_sync(FULL, acc.z, o);
        acc.w += __shfl_xor_sync(FULL, acc.w, o);
        lsum  += __shfl_xor_sync(FULL, lsum,  o);
    }
    const float inv = (lsum > 0.f) ? (1.f / lsum) : 0.f;

    if (lane < 8) {
        float4 r;
        r.x = acc.x * inv + bq.x;
        r.y = acc.y * inv + bq.y;
        r.z = acc.z * inv + bq.z;
        r.w = acc.w * inv + bq.w;
        *reinterpret_cast<float4*>(&out[(size_t)node * ODIM + lane * 4]) = r;
    }
}

extern "C" void kernel_launch(void* const* d_in, const int* in_sizes, int n_in,
                              void* d_out, int out_size) {
    const float* X   = (const float*)d_in[0];
    const float* K   = (const float*)d_in[1];
    const float* V   = (const float*)d_in[2];
    const float* Wo  = (const float*)d_in[3];
    const float* bo  = (const float*)d_in[4];
    const int*   src = (const int*)d_in[5];
    const int*   dst = (const int*)d_in[6];

    const int N = in_sizes[0] / DK;   // 100000
    const int E = in_sizes[5];        // 1600000

    const int vkBlocks = (N + 63) / 64;                  // 1563
    const int rpBlocks = ((E + 3) / 4 + 255) / 256;      // 1563
    prep_kernel<<<vkBlocks + rpBlocks, 256>>>(K, V, Wo, dst, N, E, vkBlocks);

    const int blocks = (N + WPB - 1) / WPB;              // one warp per node; 25000
    gat_kernel<<<blocks, 32 * WPB>>>(X, bo, src, (float*)d_out, N);
}

// round 15
// speedup vs baseline: 1.2596x; 1.1204x over previous
#include <cuda_runtime.h>
#include <cuda_fp16.h>

#define DK 32
#define ODIM 32
#define MAX_NODES 100002
#define MAX_N 100000
#define WPB 4            // warps per block (block = 128 threads)

// Scratch (device globals — no allocation in kernel_launch)
__device__ int g_row_ptr[MAX_NODES];
// Packed per-node 128B line of 16B chunks; chunk qd = [K' quad qd | V' quad qd]
// halves, where K' = K/DK (scale folded) and V' = V @ Wo (projection folded).
__device__ __align__(16) __half g_KV[MAX_N * 2 * DK];

// ---------------------------------------------------------------------------
// Prep kernel (fused, 2 block ranges):
//   [0, vkBlocks)  : per 64-node tile — pack K'/DK + compute V' = V @ Wo,
//                    stage both in smem, write full 128B lines coalesced.
//   remainder      : CSR row pointers (4 edges/thread, int4)
// ---------------------------------------------------------------------------
__global__ __launch_bounds__(256) void prep_kernel(
    const float* __restrict__ Kf,
    const float* __restrict__ Vf,
    const float* __restrict__ Wo,
    const int*   __restrict__ dst,
    int N, int E, int vkBlocks)
{
    __shared__ float4 sWoT4[ODIM][9];                  // sWoT4[c][dq] = Wo[4dq..][c]
    __shared__ __align__(16) float sV[64 * DK];        // 64-node V tile
    __shared__ __align__(16) __half sPack[64 * 64];    // staged [K'|V'] lines

    const int b = (int)blockIdx.x;
    if (b < vkBlocks) {
        const int tile = b * 64;
        const int tid  = threadIdx.x;

        for (int i = tid; i < DK * ODIM; i += 256) {
            const int d = i >> 5, c = i & 31;
            reinterpret_cast<float*>(&sWoT4[c][0])[d] = Wo[i];
        }
        for (int i = tid; i < 64 * DK / 4; i += 256) {
            const int gidx = tile * (DK / 4) + i;
            float4 v = make_float4(0.f, 0.f, 0.f, 0.f);
            if (gidx < N * (DK / 4))
                v = reinterpret_cast<const float4*>(Vf)[gidx];
            reinterpret_cast<float4*>(sV)[i] = v;
        }
        for (int i = tid; i < 64 * 8; i += 256) {
            const int nl = i >> 3;        // local node
            const int qd = i & 7;
            const int gn = tile + nl;
            if (gn < N) {
                const float4 kq = reinterpret_cast<const float4*>(Kf)[(size_t)gn * 8 + qd];
                __half2 h0 = __floats2half2_rn(kq.x * (1.f/DK), kq.y * (1.f/DK));
                __half2 h1 = __floats2half2_rn(kq.z * (1.f/DK), kq.w * (1.f/DK));
                uint2 o;
                o.x = *reinterpret_cast<unsigned*>(&h0);
                o.y = *reinterpret_cast<unsigned*>(&h1);
                *reinterpret_cast<uint2*>(&sPack[nl * 64 + qd * 8]) = o;
            }
        }
        __syncthreads();

        {
            const int lane = threadIdx.x & 31;
            const int w    = threadIdx.x >> 5;
            float o[8];
            #pragma unroll
            for (int n = 0; n < 8; ++n) o[n] = 0.f;
            #pragma unroll
            for (int dq = 0; dq < 8; ++dq) {
                const float4 wt = sWoT4[lane][dq];
                #pragma unroll
                for (int n = 0; n < 8; ++n) {
                    const float4 a = *reinterpret_cast<const float4*>(&sV[(w * 8 + n) * DK + dq * 4]);
                    o[n] += a.x * wt.x + a.y * wt.y + a.z * wt.z + a.w * wt.w;
                }
            }
            #pragma unroll
            for (int n = 0; n < 8; ++n)
                sPack[(w * 8 + n) * 64 + (lane >> 2) * 8 + 4 + (lane & 3)] =
                    __float2half_rn(o[n]);
        }
        __syncthreads();

        for (int i = tid; i < 64 * 8; i += 256) {
            const int nl = i >> 3;
            const int gn = tile + nl;
            if (gn < N)
                reinterpret_cast<uint4*>(g_KV)[(size_t)gn * 8 + (i & 7)] =
                    reinterpret_cast<const uint4*>(sPack)[i];
        }
    } else {
        // ---- Row pointers: 4 edges per thread ----
        const int t  = (b - vkBlocks) * 256 + threadIdx.x;
        const int e0 = t * 4;
        if (e0 >= E) return;
        int ds[4];
        if (e0 + 3 < E) {
            const int4 d4 = *reinterpret_cast<const int4*>(dst + e0);
            ds[0] = d4.x; ds[1] = d4.y; ds[2] = d4.z; ds[3] = d4.w;
        } else {
            #pragma unroll
            for (int j = 0; j < 4; ++j) ds[j] = (e0 + j < E) ? dst[e0 + j] : 0;
        }
        int p = (e0 > 0) ? dst[e0 - 1] : -1;
        #pragma unroll
        for (int j = 0; j < 4; ++j) {
            const int e = e0 + j;
            if (e < E) {
                const int d = ds[j];
                for (int n = p + 1; n <= d; ++n) g_row_ptr[n] = e;
                p = d;
                if (e == E - 1)
                    for (int n = d + 1; n <= N; ++n) g_row_ptr[n] = E;
            }
        }
    }
}

// ---------------------------------------------------------------------------
// Fused gat kernel: ONE warp per node; 8-lane groups fetch ONE packed [K'|V']
// line per edge; two independent 4-edge sub-batches per iteration (MLP=2).
// Dot path in fp16 (HMUL2/HFMA2 + packed half2 xor-reduction of both edges).
// V' accumulation stays fp32. Epilogue = reduce + rcp + one 128B store.
// ---------------------------------------------------------------------------
__global__ __launch_bounds__(128, 13) void gat_kernel(
    const float* __restrict__ X,
    const float* __restrict__ bo,
    const int*   __restrict__ src,
    float* __restrict__ out,
    int N)
{
    const unsigned FULL = 0xffffffffu;
    const int lane = threadIdx.x & 31;
    const int node = (blockIdx.x * blockDim.x + threadIdx.x) >> 5;
    if (node >= N) return;

    const int g  = lane >> 3;   // edge slot within a 4-edge sub-batch
    const int qd = lane & 7;    // quad (4 dims) this lane covers

    float4 bq = make_float4(0.f, 0.f, 0.f, 0.f);
    if (lane < 8) bq = reinterpret_cast<const float4*>(bo)[lane];

    const int beg = g_row_ptr[node];
    const int end = g_row_ptr[node + 1];

    // Query quad as two half2 (1/DK is folded into K').
    const float4 q4 = *reinterpret_cast<const float4*>(X + (size_t)node * DK + qd * 4);
    const __half2 qh0 = __floats2half2_rn(q4.x, q4.y);
    const __half2 qh1 = __floats2half2_rn(q4.z, q4.w);

    float4 acc = make_float4(0.f, 0.f, 0.f, 0.f);
    float lsum = 0.f;

    int base = beg;
    // Full (unmasked) iterations: 8 edges = 2 independent sub-batches of 4.
    #pragma unroll 1
    for (; base + 8 <= end; base += 8) {
        const unsigned oA = (unsigned)__ldg(&src[base + g])     * 8u + qd;
        const unsigned oB = (unsigned)__ldg(&src[base + 4 + g]) * 8u + qd;
        const uint4 ha = reinterpret_cast<const uint4*>(g_KV)[oA];
        const uint4 hb = reinterpret_cast<const uint4*>(g_KV)[oB];

        // fp16 partial dots for both edges.
        __half2 pa = __hmul2(*reinterpret_cast<const __half2*>(&ha.x), qh0);
        pa = __hfma2(*reinterpret_cast<const __half2*>(&ha.y), qh1, pa);
        __half2 pb = __hmul2(*reinterpret_cast<const __half2*>(&hb.x), qh0);
        pb = __hfma2(*reinterpret_cast<const __half2*>(&hb.y), qh1, pb);
        // dAB = (sum(pa), sum(pb)) packed in one half2.
        __half2 dAB = __hadd2(__halves2half2(__low2half(pa), __low2half(pb)),
                              __halves2half2(__high2half(pa), __high2half(pb)));
        // Reduce both dots across the 8-lane group in one shuffle stream.
        unsigned u = *reinterpret_cast<unsigned*>(&dAB);
        #pragma unroll
        for (int o = 1; o <= 4; o <<= 1) {
            const unsigned v = __shfl_xor_sync(FULL, u, o);
            const __half2 t = __hadd2(*reinterpret_cast<const __half2*>(&u),
                                      *reinterpret_cast<const __half2*>(&v));
            u = *reinterpret_cast<const unsigned*>(&t);
        }
        const __half2 d2 = *reinterpret_cast<const __half2*>(&u);
        const float pA = __expf(__low2float(d2));
        const float pB = __expf(__high2float(d2));
        lsum += pA + pB;

        const float2 va0 = __half22float2(*reinterpret_cast<const __half2*>(&ha.z));
        const float2 va1 = __half22float2(*reinterpret_cast<const __half2*>(&ha.w));
        const float2 vb0 = __half22float2(*reinterpret_cast<const __half2*>(&hb.z));
        const float2 vb1 = __half22float2(*reinterpret_cast<const __half2*>(&hb.w));
        acc.x += pA * va0.x + pB * vb0.x;
        acc.y += pA * va0.y + pB * vb0.y;
        acc.z += pA * va1.x + pB * vb1.x;
        acc.w += pA * va1.y + pB * vb1.y;
    }

    // One masked tail iteration.
    if (base < end) {
        const int eA = base + g;
        const int eB = base + 4 + g;
        const bool mA = (eA < end);
        const bool mB = (eB < end);
        const unsigned oA = (unsigned)__ldg(&src[mA ? eA : beg]) * 8u + qd;
        const unsigned oB = (unsigned)__ldg(&src[mB ? eB : beg]) * 8u + qd;
        const uint4 ha = reinterpret_cast<const uint4*>(g_KV)[oA];
        const uint4 hb = reinterpret_cast<const uint4*>(g_KV)[oB];

        __half2 pa = __hmul2(*reinterpret_cast<const __half2*>(&ha.x), qh0);
        pa = __hfma2(*reinterpret_cast<const __half2*>(&ha.y), qh1, pa);
        __half2 pb = __hmul2(*reinterpret_cast<const __half2*>(&hb.x), qh0);
        pb = __hfma2(*reinterpret_cast<const __half2*>(&hb.y), qh1, pb);
        __half2 dAB = __hadd2(__halves2half2(__low2half(pa), __low2half(pb)),
                              __halves2half2(__high2half(pa), __high2half(pb)));
        unsigned u = *reinterpret_cast<unsigned*>(&dAB);
        #pragma unroll
        for (int o = 1; o <= 4; o <<= 1) {
            const unsigned v = __shfl_xor_sync(FULL, u, o);
            const __half2 t = __hadd2(*reinterpret_cast<const __half2*>(&u),
                                      *reinterpret_cast<const __half2*>(&v));
            u = *reinterpret_cast<const unsigned*>(&t);
        }
        const __half2 d2 = *reinterpret_cast<const __half2*>(&u);
        const float pA = mA ? __expf(__low2float(d2)) : 0.f;
        const float pB = mB ? __expf(__high2float(d2)) : 0.f;
        lsum += pA + pB;

        const float2 va0 = __half22float2(*reinterpret_cast<const __half2*>(&ha.z));
        const float2 va1 = __half22float2(*reinterpret_cast<const __half2*>(&ha.w));
        const float2 vb0 = __half22float2(*reinterpret_cast<const __half2*>(&hb.z));
        const float2 vb1 = __half22float2(*reinterpret_cast<const __half2*>(&hb.w));
        acc.x += pA * va0.x + pB * vb0.x;
        acc.y += pA * va0.y + pB * vb0.y;
        acc.z += pA * va1.x + pB * vb1.x;
        acc.w += pA * va1.y + pB * vb1.y;
    }

    // Reduce acc + lsum across the 4 edge-groups (bits 3,4 only).
    #pragma unroll
    for (int o = 8; o <= 16; o <<= 1) {
        acc.x += __shfl_xor_sync(FULL, acc.x, o);
        acc.y += __shfl_xor_sync(FULL, acc.y, o);
        acc.z += __shfl_xor_sync(FULL, acc.z, o);
        acc.w += __shfl_xor_sync(FULL, acc.w, o);
        lsum  += __shfl_xor_sync(FULL, lsum,  o);
    }
    const float inv = (lsum > 0.f) ? (1.f / lsum) : 0.f;

    // Projection already folded into V': lanes 0..7 hold output quads 0..7.
    if (lane < 8) {
        float4 r;
        r.x = acc.x * inv + bq.x;
        r.y = acc.y * inv + bq.y;
        r.z = acc.z * inv + bq.z;
        r.w = acc.w * inv + bq.w;
        *reinterpret_cast<float4*>(&out[(size_t)node * ODIM + lane * 4]) = r;
    }
}

extern "C" void kernel_launch(void* const* d_in, const int* in_sizes, int n_in,
                              void* d_out, int out_size) {
    const float* X   = (const float*)d_in[0];
    const float* K   = (const float*)d_in[1];
    const float* V   = (const float*)d_in[2];
    const float* Wo  = (const float*)d_in[3];
    const float* bo  = (const float*)d_in[4];
    const int*   src = (const int*)d_in[5];
    const int*   dst = (const int*)d_in[6];

    const int N = in_sizes[0] / DK;   // 100000
    const int E = in_sizes[5];        // 1600000

    const int vkBlocks = (N + 63) / 64;                  // 1563
    const int rpBlocks = ((E + 3) / 4 + 255) / 256;      // 1563
    prep_kernel<<<vkBlocks + rpBlocks, 256>>>(K, V, Wo, dst, N, E, vkBlocks);

    const int blocks = (N + WPB - 1) / WPB;              // one warp per node; 25000
    gat_kernel<<<blocks, 32 * WPB>>>(X, bo, src, (float*)d_out, N);
}